// round 8
// baseline (speedup 1.0000x reference)
#include <cuda_runtime.h>

// Problem constants
constexpr int NB = 32;    // batch
constexpr int NT = 1024;  // tokens (32x32)
constexpr int NF = 768;   // features
constexpr int NS = 32;    // splits per batch in pass C
constexpr int TOK_PER_BLK  = NT / NS;       // 32 tokens per kC block
constexpr int TOK_PER_WARP = TOK_PER_BLK/8; // 4 tokens per warp
constexpr int BLK_PER_BATCH_A = NT / 8;     // 128 kA blocks per batch

// Scratch (device globals — no allocations; counters self-reset per launch)
__device__ float4 g_meta[NB * NT];   // {rnorm, p1, tok.fw0, tok.fw1}
__device__ float  g_q[NB * NF];      // normalized argmax token per batch
__device__ float  g_d0[NB * NS];
__device__ float  g_d1[NB * NS];
__device__ float  g_u [NB * NS];
__device__ unsigned g_cntA[NB];
__device__ unsigned g_cntC;

// ---------------------------------------------------------------------------
// Kernel A: one warp per token. Computes ||tok||, tok.fc_w{0,1} (-> p1) and
// tok.fc_final_w{0,1} (pre-projections used by kC). Packs all four per-token
// scalars into one float4. Last-finishing block per batch does the argmax
// (first-max tiebreak, matches jnp.argmax) and writes q = tok[idx]*rnorm.
// ---------------------------------------------------------------------------
__global__ __launch_bounds__(256) void kA(const float* __restrict__ x,
                                          const float* __restrict__ fc_w,
                                          const float* __restrict__ fc_b,
                                          const float* __restrict__ fc_final_w) {
    const int warp = threadIdx.x >> 5;
    const int lane = threadIdx.x & 31;
    const int g = blockIdx.x * 8 + warp;          // global token id
    const int b = blockIdx.x / BLK_PER_BATCH_A;   // batch of this block

    __shared__ float ws[4 * NF];                  // 12 KB: fc_w0,1 + fcf_w0,1
    for (int i = threadIdx.x; i < 2 * NF; i += 256) ws[i] = fc_w[i];
    for (int i = threadIdx.x; i < 2 * NF; i += 256) ws[2 * NF + i] = fc_final_w[i];
    __syncthreads();
    const float4* w0 = reinterpret_cast<const float4*>(ws);
    const float4* w1 = reinterpret_cast<const float4*>(ws + NF);
    const float4* f0 = reinterpret_cast<const float4*>(ws + 2 * NF);
    const float4* f1 = reinterpret_cast<const float4*>(ws + 3 * NF);

    const float4* tok = reinterpret_cast<const float4*>(x + (size_t)g * NF);

    float nrm = 0.f, d0 = 0.f, d1 = 0.f, e0 = 0.f, e1 = 0.f;
#pragma unroll
    for (int i = 0; i < 6; i++) {
        float4 v = tok[lane + 32 * i];
        float4 a = w0[lane + 32 * i];
        float4 c = w1[lane + 32 * i];
        float4 p = f0[lane + 32 * i];
        float4 q = f1[lane + 32 * i];
        nrm += v.x * v.x + v.y * v.y + v.z * v.z + v.w * v.w;
        d0  += v.x * a.x + v.y * a.y + v.z * a.z + v.w * a.w;
        d1  += v.x * c.x + v.y * c.y + v.z * c.z + v.w * c.w;
        e0  += v.x * p.x + v.y * p.y + v.z * p.z + v.w * p.w;
        e1  += v.x * q.x + v.y * q.y + v.z * q.z + v.w * q.w;
    }
#pragma unroll
    for (int o = 16; o; o >>= 1) {
        nrm += __shfl_xor_sync(0xffffffffu, nrm, o);
        d0  += __shfl_xor_sync(0xffffffffu, d0, o);
        d1  += __shfl_xor_sync(0xffffffffu, d1, o);
        e0  += __shfl_xor_sync(0xffffffffu, e0, o);
        e1  += __shfl_xor_sync(0xffffffffu, e1, o);
    }
    if (lane == 0) {
        const float p1 = 1.f / (1.f + expf((d0 + fc_b[0]) - (d1 + fc_b[1])));
        g_meta[g] = make_float4(rsqrtf(nrm), p1, e0, e1);
    }
    __syncthreads();

    // Single release fence per block (syncthreads orders all block writes
    // before thread 0's gpu-scope fence + atomic).
    __shared__ unsigned s_last;
    if (threadIdx.x == 0) {
        __threadfence();
        s_last = atomicAdd(&g_cntA[b], 1u);
    }
    __syncthreads();
    if (s_last != BLK_PER_BATCH_A - 1) return;
    __threadfence();  // acquire: see all blocks' meta writes

    // argmax over 1024 p1 values, 256 threads x 4 candidates.
    // Comparator (v>best)||(v==best && i<besti) => global first-max.
    float bestv = -1.f; int besti = 0;
#pragma unroll
    for (int k = 0; k < 4; k++) {
        const int t = threadIdx.x + 256 * k;
        const float v = g_meta[b * NT + t].y;
        if (v > bestv || (v == bestv && t < besti)) { bestv = v; besti = t; }
    }
#pragma unroll
    for (int o = 16; o; o >>= 1) {
        float v2 = __shfl_xor_sync(0xffffffffu, bestv, o);
        int   i2 = __shfl_xor_sync(0xffffffffu, besti, o);
        if (v2 > bestv || (v2 == bestv && i2 < besti)) { bestv = v2; besti = i2; }
    }
    __shared__ float swv[8];
    __shared__ int   swi[8];
    if (lane == 0) { swv[warp] = bestv; swi[warp] = besti; }
    __syncthreads();
    __shared__ int s_idx;
    if (threadIdx.x == 0) {
        float bv = swv[0]; int bi = swi[0];
#pragma unroll
        for (int w = 1; w < 8; w++)
            if (swv[w] > bv || (swv[w] == bv && swi[w] < bi)) { bv = swv[w]; bi = swi[w]; }
        s_idx = bi;
        g_cntA[b] = 0;  // reset for next graph replay
    }
    __syncthreads();
    const int idx = s_idx;
    const float rn = g_meta[b * NT + idx].x;
    const float* qt = x + ((size_t)b * NT + idx) * NF;
    for (int f = threadIdx.x; f < NF; f += 256)
        g_q[b * NF + f] = qt[f] * rn;
}

// ---------------------------------------------------------------------------
// Kernel C: streaming scoring pass. grid = (NS, NB), 256 threads.
// Per token: ONE dot product s = q.tok (warp-reduced), u = exp(s*rn)*p1,
// then scalar FMAs into (U, D0, D1) using the pre-projections from kA.
// No per-feature accumulator -> low registers -> high occupancy.
// Last-finishing block of the grid reduces all splits and writes output.
// ---------------------------------------------------------------------------
__global__ __launch_bounds__(256) void kC(const float* __restrict__ x,
                                          const float* __restrict__ fc_final_b,
                                          float* __restrict__ out) {
    const int b    = blockIdx.y;
    const int sp   = blockIdx.x;
    const int warp = threadIdx.x >> 5;
    const int lane = threadIdx.x & 31;

    __shared__ float4 q4s[NF / 4];     // 3 KB
    __shared__ float  s0[8], s1[8], su[8];

    const float4* q4 = reinterpret_cast<const float4*>(g_q + b * NF);
    for (int i = threadIdx.x; i < NF / 4; i += 256) q4s[i] = q4[i];
    __syncthreads();

    float U = 0.f, D0 = 0.f, D1 = 0.f;

    const int t0 = sp * TOK_PER_BLK + warp * TOK_PER_WARP;
#pragma unroll
    for (int tt = 0; tt < TOK_PER_WARP; tt++) {
        const int t = t0 + tt;
        const float4 m = g_meta[b * NT + t];   // {rnorm, p1, dw0, dw1}
        const float4* tok = reinterpret_cast<const float4*>(x + ((size_t)b * NT + t) * NF);
        float s = 0.f;
#pragma unroll
        for (int i = 0; i < 6; i++) {
            float4 v = tok[lane + 32 * i];
            float4 q = q4s[lane + 32 * i];
            s += v.x * q.x + v.y * q.y + v.z * q.z + v.w * q.w;
        }
#pragma unroll
        for (int o = 16; o; o >>= 1) s += __shfl_xor_sync(0xffffffffu, s, o);
        const float u = expf(s * m.x) * m.y;   // lane-replicated
        U  += u;
        D0 += u * m.z;
        D1 += u * m.w;
    }

    // U/D0/D1 are lane-replicated: take lane 0's values only (no shuffle!).
    if (lane == 0) { s0[warp] = D0; s1[warp] = D1; su[warp] = U; }
    __syncthreads();

    __shared__ unsigned s_last;
    if (threadIdx.x == 0) {
        float A0 = 0.f, A1 = 0.f, AU = 0.f;
#pragma unroll
        for (int w = 0; w < 8; w++) { A0 += s0[w]; A1 += s1[w]; AU += su[w]; }
        g_d0[b * NS + sp] = A0;
        g_d1[b * NS + sp] = A1;
        g_u [b * NS + sp] = AU;
        __threadfence();
        s_last = atomicAdd(&g_cntC, 1u);
    }
    __syncthreads();
    if (s_last != (unsigned)(NB * NS - 1)) return;
    __threadfence();  // acquire all blocks' partials

    // Final reduce: threads 0..31 each own one batch; fixed summation order.
    if (threadIdx.x < NB) {
        const int bb = threadIdx.x;
        float A0 = 0.f, A1 = 0.f, AU = 0.f;
#pragma unroll
        for (int s = 0; s < NS; s++) {
            A0 += g_d0[bb * NS + s];
            A1 += g_d1[bb * NS + s];
            AU += g_u [bb * NS + s];
        }
        const float invU = 1.f / AU;
        out[bb * 2 + 0] = A0 * invU + fc_final_b[0];
        out[bb * 2 + 1] = A1 * invU + fc_final_b[1];
    }
    if (threadIdx.x == 0) g_cntC = 0;  // reset for next replay
}

// ---------------------------------------------------------------------------
extern "C" void kernel_launch(void* const* d_in, const int* in_sizes, int n_in,
                              void* d_out, int out_size) {
    const float* x          = (const float*)d_in[0];
    const float* fc_w       = (const float*)d_in[1];
    const float* fc_b       = (const float*)d_in[2];
    const float* fc_final_w = (const float*)d_in[3];
    const float* fc_final_b = (const float*)d_in[4];
    float* out = (float*)d_out;

    kA<<<NB * NT / 8, 256>>>(x, fc_w, fc_b, fc_final_w);
    dim3 gridC(NS, NB);
    kC<<<gridC, 256>>>(x, fc_final_b, out);
}